// round 2
// baseline (speedup 1.0000x reference)
#include <cuda_runtime.h>
#include <cstdint>

// Fixed-degree SpMM: out[n,b] = sum_k values[n,k] * x[indices[n,k],b] + bias[n]
// N = 1,000,000, K = 32, B = 8. Inputs (metadata order): x[N,8] f32, values[N,32] f32,
// bias[N] f32, indices[N,32] i32. Output: out[N,8] f32.
//
// Layout: 128 neurons per 256-thread block. Stage indices/values into smem with a
// transposed, padded layout (coalesced 16B global loads, conflict-free smem on both
// sides). Compute: 2 lanes per neuron, each lane owns a float4 half-row of x/out.

#define KSYN    32
#define BCOLS   8
#define NB      128          // neurons per block
#define TPB     256
#define SPITCH  129          // smem pitch (NB+1) -> conflict-free

__global__ __launch_bounds__(TPB) void cortical_spmm_kernel(
    const float* __restrict__ x,
    const float* __restrict__ values,
    const float* __restrict__ bias,
    const int*   __restrict__ indices,
    float*       __restrict__ out,
    int N)
{
    __shared__ int   s_idx[KSYN * SPITCH];
    __shared__ float s_val[KSYN * SPITCH];

    const int block_n0 = blockIdx.x * NB;
    const int t = threadIdx.x;

    // ---- Stage indices/values: coalesced 16B loads, transposed smem writes ----
    // Elements this block owns: remaining*32 (always a multiple of 4).
    int remaining = N - block_n0;
    if (remaining > NB) remaining = NB;
    const int n_vec = (remaining * KSYN) >> 2;   // # of int4/float4 vectors

    const int4*   gidx = reinterpret_cast<const int4*>(indices + (size_t)block_n0 * KSYN);
    const float4* gval = reinterpret_cast<const float4*>(values + (size_t)block_n0 * KSYN);

    for (int i4 = t; i4 < n_vec; i4 += TPB) {
        int4   iv = __ldcs(gidx + i4);   // streaming: don't evict x from L2
        float4 fv = __ldcs(gval + i4);
        const int n  = i4 >> 3;           // local neuron (8 vectors per neuron)
        const int k0 = (i4 & 7) << 2;     // starting k of this vector
        s_idx[(k0 + 0) * SPITCH + n] = iv.x;
        s_idx[(k0 + 1) * SPITCH + n] = iv.y;
        s_idx[(k0 + 2) * SPITCH + n] = iv.z;
        s_idx[(k0 + 3) * SPITCH + n] = iv.w;
        s_val[(k0 + 0) * SPITCH + n] = fv.x;
        s_val[(k0 + 1) * SPITCH + n] = fv.y;
        s_val[(k0 + 2) * SPITCH + n] = fv.z;
        s_val[(k0 + 3) * SPITCH + n] = fv.w;
    }
    __syncthreads();

    // ---- Compute: warp = 16 neurons x 2 lanes; each lane owns a float4 half-row ----
    const int warp = t >> 5;
    const int lane = t & 31;
    const int g    = lane >> 1;          // neuron-in-warp 0..15
    const int half = lane & 1;           // which half of the 8-wide row
    const int nl   = warp * 16 + g;      // local neuron 0..127
    const int n    = block_n0 + nl;

    if (n < N) {
        const float4* __restrict__ xr = reinterpret_cast<const float4*>(x);

        float4 acc;
        acc.x = 0.f; acc.y = 0.f; acc.z = 0.f; acc.w = 0.f;

        #pragma unroll 8
        for (int k = 0; k < KSYN; k++) {
            const int   idx = s_idx[k * SPITCH + nl];
            const float v   = s_val[k * SPITCH + nl];
            const float4 xv = __ldg(xr + ((size_t)idx * 2 + half));
            acc.x = fmaf(v, xv.x, acc.x);
            acc.y = fmaf(v, xv.y, acc.y);
            acc.z = fmaf(v, xv.z, acc.z);
            acc.w = fmaf(v, xv.w, acc.w);
        }

        const float b = __ldg(bias + n);
        acc.x += b; acc.y += b; acc.z += b; acc.w += b;

        reinterpret_cast<float4*>(out)[(size_t)n * 2 + half] = acc;
    }
}

extern "C" void kernel_launch(void* const* d_in, const int* in_sizes, int n_in,
                              void* d_out, int out_size)
{
    const float* x       = (const float*)d_in[0];
    const float* values  = (const float*)d_in[1];
    const float* bias    = (const float*)d_in[2];
    const int*   indices = (const int*)d_in[3];
    float*       out     = (float*)d_out;

    const int N = in_sizes[2];           // bias has N elements
    const int grid = (N + NB - 1) / NB;

    cortical_spmm_kernel<<<grid, TPB>>>(x, values, bias, indices, out, N);
}

// round 4
// speedup vs baseline: 1.0177x; 1.0177x over previous
#include <cuda_runtime.h>
#include <cstdint>

// Fixed-degree SpMM: out[n,b] = sum_k values[n,k] * x[indices[n,k],b] + bias[n]
// N = 1,000,000, K = 32, B = 8.
//
// 128 neurons / 256-thread block. indices/values staged to smem in a transposed
// [k][n] layout with XOR swizzle (no padding -> 32KB -> 7 blocks/SM).
// Compute: 2 lanes per neuron, each lane owns one float4 half-row of x/out,
// so each random gather costs exactly one 128B-line wavefront at L1 and one
// 32B sector at L2 (both minimal).
//
// Swizzle: word offset = k*128 + (n ^ (k & 28)).
//  - writes (lane l: n=nb+(l>>3), k0=4*(l&7)): bank = (nb+b)^(4a) -> 32 distinct.
//  - reads  (fixed k, 16 consecutive n, 2-lane broadcast): permutation -> conflict-free.

#define KSYN 32
#define NB   128
#define TPB  256

__global__ __launch_bounds__(TPB, 7) void cortical_spmm_kernel(
    const float* __restrict__ x,
    const float* __restrict__ values,
    const float* __restrict__ bias,
    const int*   __restrict__ indices,
    float*       __restrict__ out,
    int N)
{
    __shared__ int   s_idx[KSYN * NB];
    __shared__ float s_val[KSYN * NB];

    const int block_n0 = blockIdx.x * NB;
    const int t = threadIdx.x;
    const int remaining = N - block_n0;

    if (remaining >= NB) {
        // ---- Full tile: 1024 int4/float4 vectors, 4 per thread.
        // Software-pipelined: round j+1's global loads issue before round j's stores.
        const int4*   gidx = reinterpret_cast<const int4*>(indices) + (size_t)block_n0 * (KSYN / 4);
        const float4* gval = reinterpret_cast<const float4*>(values) + (size_t)block_n0 * (KSYN / 4);

        int4   iv = __ldcs(gidx + t);
        float4 fv = __ldcs(gval + t);

        #pragma unroll
        for (int j = 0; j < 4; j++) {
            int4   iv_n;
            float4 fv_n;
            if (j < 3) {
                iv_n = __ldcs(gidx + t + (j + 1) * TPB);
                fv_n = __ldcs(gval + t + (j + 1) * TPB);
            }
            const int i4 = t + j * TPB;
            const int n  = i4 >> 3;            // local neuron
            const int k0 = (i4 & 7) << 2;      // starting k of this vector
            const int sw = n ^ k0;             // (k0+e)&28 == k0 for e<4
            s_idx[(k0 + 0) * NB + sw] = iv.x;
            s_idx[(k0 + 1) * NB + sw] = iv.y;
            s_idx[(k0 + 2) * NB + sw] = iv.z;
            s_idx[(k0 + 3) * NB + sw] = iv.w;
            s_val[(k0 + 0) * NB + sw] = fv.x;
            s_val[(k0 + 1) * NB + sw] = fv.y;
            s_val[(k0 + 2) * NB + sw] = fv.z;
            s_val[(k0 + 3) * NB + sw] = fv.w;
            iv = iv_n;
            fv = fv_n;
        }
    } else {
        // ---- Partial last tile: generic path.
        const int n_vec = (remaining * KSYN) >> 2;
        const int4*   gidx = reinterpret_cast<const int4*>(indices) + (size_t)block_n0 * (KSYN / 4);
        const float4* gval = reinterpret_cast<const float4*>(values) + (size_t)block_n0 * (KSYN / 4);
        for (int i4 = t; i4 < n_vec; i4 += TPB) {
            int4   iv = __ldcs(gidx + i4);
            float4 fv = __ldcs(gval + i4);
            const int n  = i4 >> 3;
            const int k0 = (i4 & 7) << 2;
            const int sw = n ^ k0;
            s_idx[(k0 + 0) * NB + sw] = iv.x;
            s_idx[(k0 + 1) * NB + sw] = iv.y;
            s_idx[(k0 + 2) * NB + sw] = iv.z;
            s_idx[(k0 + 3) * NB + sw] = iv.w;
            s_val[(k0 + 0) * NB + sw] = fv.x;
            s_val[(k0 + 1) * NB + sw] = fv.y;
            s_val[(k0 + 2) * NB + sw] = fv.z;
            s_val[(k0 + 3) * NB + sw] = fv.w;
        }
    }
    __syncthreads();

    // ---- Compute: warp = 16 neurons x 2 lanes; each lane owns a float4 half-row.
    const int warp = t >> 5;
    const int lane = t & 31;
    const int g    = lane >> 1;
    const int half = lane & 1;
    const int nl   = warp * 16 + g;
    const int n    = block_n0 + nl;

    if (n < N) {
        const float4* __restrict__ xr = reinterpret_cast<const float4*>(x);

        float4 acc;
        acc.x = 0.f; acc.y = 0.f; acc.z = 0.f; acc.w = 0.f;

        #pragma unroll
        for (int k = 0; k < KSYN; k++) {
            const int   w   = k * NB + (nl ^ (k & 28));
            const int   idx = s_idx[w];
            const float v   = s_val[w];
            const float4 xv = __ldg(xr + ((size_t)(unsigned)idx * 2 + half));
            acc.x = fmaf(v, xv.x, acc.x);
            acc.y = fmaf(v, xv.y, acc.y);
            acc.z = fmaf(v, xv.z, acc.z);
            acc.w = fmaf(v, xv.w, acc.w);
        }

        const float b = __ldg(bias + n);
        acc.x += b; acc.y += b; acc.z += b; acc.w += b;

        __stcs(reinterpret_cast<float4*>(out) + (size_t)n * 2 + half, acc);
    }
}

extern "C" void kernel_launch(void* const* d_in, const int* in_sizes, int n_in,
                              void* d_out, int out_size)
{
    const float* x       = (const float*)d_in[0];
    const float* values  = (const float*)d_in[1];
    const float* bias    = (const float*)d_in[2];
    const int*   indices = (const int*)d_in[3];
    float*       out     = (float*)d_out;

    const int N = in_sizes[2];           // bias has N elements
    const int grid = (N + NB - 1) / NB;

    cortical_spmm_kernel<<<grid, TPB>>>(x, values, bias, indices, out, N);
}